// round 1
// baseline (speedup 1.0000x reference)
#include <cuda_runtime.h>
#include <math.h>

#define BB 8
#define HH 128
#define WW 128
#define CC 64
#define KK 9

// Scratch (allocation-free rule: __device__ globals)
__device__ __align__(16) float  g_xt[BB*HH*WW*CC];   // NHWC x
__device__ __align__(16) float4 g_coef[BB*HH*WW];    // sin, cos, wr*r, wr
__device__ __align__(16) float  g_wt[KK*CC*CC];      // [k][c][o]
__device__ __align__(16) float  g_wcoef[KK*CC*4];    // [pos][c][o4] o4 = {sin,cos,str,whl}

// ---------------------------------------------------------------------------
// K0: NCHW -> NHWC transpose (per batch: 64 x 16384 matrix transpose)
// ---------------------------------------------------------------------------
__global__ void k_transpose(const float* __restrict__ x) {
    __shared__ float sm[32][33];
    int b  = blockIdx.z;
    int c0 = blockIdx.y * 32;
    int s0 = blockIdx.x * 32;
    int tx = threadIdx.x, ty = threadIdx.y;   // 32 x 8
#pragma unroll
    for (int i = 0; i < 4; i++) {
        int c = c0 + ty + i * 8;
        sm[ty + i * 8][tx] = x[(b * CC + c) * (HH * WW) + s0 + tx];
    }
    __syncthreads();
#pragma unroll
    for (int i = 0; i < 4; i++) {
        int s = s0 + ty + i * 8;
        g_xt[(size_t)(b * (HH * WW) + s) * CC + c0 + tx] = sm[tx][ty + i * 8];
    }
}

// ---------------------------------------------------------------------------
// K1: weight reorder
// ---------------------------------------------------------------------------
__global__ void k_wprep(const float* __restrict__ wmain,
                        const float* __restrict__ wrot,
                        const float* __restrict__ wstr,
                        const float* __restrict__ wwhl) {
    int idx = blockIdx.x * 256 + threadIdx.x;
    if (idx < KK * CC * CC) {
        int o = idx % CC;
        int c = (idx / CC) % CC;
        int k = idx / (CC * CC);
        g_wt[idx] = wmain[(o * CC + c) * KK + k];
    }
    if (idx < KK * CC * 4) {
        int o   = idx & 3;
        int c   = (idx >> 2) % CC;
        int pos = idx / (CC * 4);
        float v;
        if (o == 0)      v = wrot[(0 * CC + c) * KK + pos];
        else if (o == 1) v = wrot[(1 * CC + c) * KK + pos];
        else if (o == 2) v = wstr[c * KK + pos];
        else             v = wwhl[c * KK + pos];
        g_wcoef[idx] = v;
    }
}

// ---------------------------------------------------------------------------
// K2: per-pixel coefficient convs (4 out channels) + activations
//     coef = (sin, cos, wr*r, wr)
// ---------------------------------------------------------------------------
__global__ void k_coef(const float* __restrict__ brot,
                       const float* __restrict__ bstr,
                       const float* __restrict__ bwhl) {
    __shared__ float swc[KK * CC * 4];   // 2304 floats
    int t = threadIdx.x;                 // 256
    for (int i = t; i < KK * CC * 4; i += 256) swc[i] = g_wcoef[i];
    __syncthreads();

    int pid = blockIdx.x * 256 + t;
    int b = pid >> 14;
    int h = (pid >> 7) & 127;
    int w = pid & 127;

    float a0 = 0.f, a1 = 0.f, a2 = 0.f, a3 = 0.f;
#pragma unroll
    for (int p = 0; p < 9; p++) {
        int y = h + p / 3 - 1;
        int x = w + p % 3 - 1;
        if ((unsigned)y >= HH || (unsigned)x >= WW) continue;
        const float4* xr  = (const float4*)(g_xt + (size_t)((b * HH + y) * WW + x) * CC);
        const float4* wr4 = (const float4*)(swc + p * CC * 4);
#pragma unroll
        for (int c4 = 0; c4 < 16; c4++) {
            float4 xv = xr[c4];
            float4 w0 = wr4[c4 * 4 + 0];
            float4 w1 = wr4[c4 * 4 + 1];
            float4 w2 = wr4[c4 * 4 + 2];
            float4 w3 = wr4[c4 * 4 + 3];
            a0 += xv.x * w0.x + xv.y * w1.x + xv.z * w2.x + xv.w * w3.x;
            a1 += xv.x * w0.y + xv.y * w1.y + xv.z * w2.y + xv.w * w3.y;
            a2 += xv.x * w0.z + xv.y * w1.z + xv.z * w2.z + xv.w * w3.z;
            a3 += xv.x * w0.w + xv.y * w1.w + xv.z * w2.w + xv.w * w3.w;
        }
    }
    float s = a0 + brot[0];
    float c = a1 + brot[1];
    float n = sqrtf(s * s + c * c + 1e-6f);
    s = s / n;
    c = c / n;
    float r  = tanhf(a2 + bstr[0]) * 1.25f + 1.75f;   // A=1.25, B=1.75
    float wl = tanhf(a3 + bwhl[0]) * 1.0f  + 2.0f;    // C=1.0,  D=2.0
    g_coef[pid] = make_float4(s, c, wl * r, wl);
}

// ---------------------------------------------------------------------------
// K3: main deform gather + contraction
// CTA = one (b,h) row of 128 pixels, 128 threads.
// Per tap k: coords -> cooperative gather into sval[64][128] (row stride 65)
//            -> register-tiled GEMM 64o x 128p (8x8 per thread)
// ---------------------------------------------------------------------------
#define SVAL_STRIDE 65
#define SMEM_BYTES  (128 * SVAL_STRIDE * 4 + CC * CC * 4 + 128 * 16 + 128 * 16)

__global__ void __launch_bounds__(128) k_main(float* __restrict__ out) {
    extern __shared__ float smem[];
    float*  sval  = smem;                                   // 128 * 65
    float*  swt   = smem + 128 * SVAL_STRIDE;               // 64 * 64
    float4* swg   = (float4*)(swt + CC * CC);               // 128 float4 weights
    int4*   sbase = (int4*)(swg + 128);                     // 128 int4 corner bases

    int t  = threadIdx.x;
    int bh = blockIdx.x;
    int b  = bh >> 7;
    int h  = bh & 127;

    // coefficients for this thread's pixel (w = t)
    float4 cf = g_coef[bh * WW + t];   // (sin, cos, wr*r, wr)

    int pg = t & 15;     // pixel group lane
    int og = t >> 4;     // output-channel group (0..7)
    int lc = t & 15;     // channel-quad lane in gather
    int gg = t >> 4;     // pixel group in gather

    float acc[8][8];
#pragma unroll
    for (int i = 0; i < 8; i++)
#pragma unroll
        for (int j = 0; j < 8; j++) acc[i][j] = 0.f;

    size_t bimg = (size_t)b * HH * WW * CC;

    for (int k = 0; k < 9; k++) {
        // --- phase 1: load W_k slice + per-pixel coords ---
        {
            const float4* wsrc = (const float4*)(g_wt + k * CC * CC);
            float4* wdst = (float4*)swt;
#pragma unroll
            for (int i = 0; i < 8; i++) wdst[t + i * 128] = wsrc[t + i * 128];
        }
        {
            float ky = (float)(k / 3 - 1);
            float kx = (float)(k % 3 - 1);
            float o0 = ky * cf.z;    // ky * wr * r
            float o1 = kx * cf.w;    // kx * wr
            float py = (float)h + cf.y * o0 + cf.x * o1;   //  cos*o0 + sin*o1
            float px = (float)t - cf.x * o0 + cf.y * o1;   // -sin*o0 + cos*o1
            float yf = floorf(py), xf = floorf(px);
            float ly = py - yf, lx = px - xf;
            int y0 = (int)yf, x0 = (int)xf;
            int y1 = y0 + 1,  x1 = x0 + 1;
            float w00 = (1.f - ly) * (1.f - lx);
            float w01 = (1.f - ly) * lx;
            float w10 = ly * (1.f - lx);
            float w11 = ly * lx;
            float vy0 = (y0 >= 0 && y0 < HH) ? 1.f : 0.f;
            float vy1 = (y1 >= 0 && y1 < HH) ? 1.f : 0.f;
            float vx0 = (x0 >= 0 && x0 < WW) ? 1.f : 0.f;
            float vx1 = (x1 >= 0 && x1 < WW) ? 1.f : 0.f;
            w00 *= vy0 * vx0; w01 *= vy0 * vx1;
            w10 *= vy1 * vx0; w11 *= vy1 * vx1;
            int yc0 = min(max(y0, 0), HH - 1);
            int yc1 = min(max(y1, 0), HH - 1);
            int xc0 = min(max(x0, 0), WW - 1);
            int xc1 = min(max(x1, 0), WW - 1);
            int4 bs;
            bs.x = (yc0 * WW + xc0) * CC;
            bs.y = (yc0 * WW + xc1) * CC;
            bs.z = (yc1 * WW + xc0) * CC;
            bs.w = (yc1 * WW + xc1) * CC;
            sbase[t] = bs;
            swg[t]   = make_float4(w00, w01, w10, w11);
        }
        __syncthreads();

        // --- phase 2: cooperative gather (16 lanes per pixel, 8 pixels/iter) ---
#pragma unroll
        for (int it = 0; it < 16; it++) {
            int p = it * 8 + gg;
            int4   bs = sbase[p];
            float4 wv = swg[p];
            const float* base = g_xt + bimg;
            float4 v0 = *(const float4*)(base + bs.x + lc * 4);
            float4 v1 = *(const float4*)(base + bs.y + lc * 4);
            float4 v2 = *(const float4*)(base + bs.z + lc * 4);
            float4 v3 = *(const float4*)(base + bs.w + lc * 4);
            float gx = wv.x * v0.x + wv.y * v1.x + wv.z * v2.x + wv.w * v3.x;
            float gy = wv.x * v0.y + wv.y * v1.y + wv.z * v2.y + wv.w * v3.y;
            float gz = wv.x * v0.z + wv.y * v1.z + wv.z * v2.z + wv.w * v3.z;
            float gw = wv.x * v0.w + wv.y * v1.w + wv.z * v2.w + wv.w * v3.w;
            float* d = sval + p * SVAL_STRIDE + lc * 4;
            d[0] = gx; d[1] = gy; d[2] = gz; d[3] = gw;
        }
        __syncthreads();

        // --- phase 3: GEMM slice: acc += W_k^T[c][o] * val[c][p] ---
#pragma unroll 4
        for (int c = 0; c < CC; c++) {
            float4 wa = *(const float4*)(swt + c * CC + og * 8);
            float4 wb = *(const float4*)(swt + c * CC + og * 8 + 4);
            float vv[8];
#pragma unroll
            for (int pp = 0; pp < 8; pp++)
                vv[pp] = sval[(pg + pp * 16) * SVAL_STRIDE + c];
#pragma unroll
            for (int pp = 0; pp < 8; pp++) {
                float v = vv[pp];
                acc[0][pp] += wa.x * v;
                acc[1][pp] += wa.y * v;
                acc[2][pp] += wa.z * v;
                acc[3][pp] += wa.w * v;
                acc[4][pp] += wb.x * v;
                acc[5][pp] += wb.y * v;
                acc[6][pp] += wb.z * v;
                acc[7][pp] += wb.w * v;
            }
        }
        __syncthreads();
    }

    // --- write out (NCHW) ---
#pragma unroll
    for (int oo = 0; oo < 8; oo++) {
        int o = og * 8 + oo;
        float* dst = out + (size_t)((b * CC + o) * HH + h) * WW;
#pragma unroll
        for (int pp = 0; pp < 8; pp++) dst[pg + pp * 16] = acc[oo][pp];
    }
}

// ---------------------------------------------------------------------------
extern "C" void kernel_launch(void* const* d_in, const int* in_sizes, int n_in,
                              void* d_out, int out_size) {
    const float* x     = (const float*)d_in[0];
    const float* wmain = (const float*)d_in[1];
    const float* wrot  = (const float*)d_in[2];
    const float* brot  = (const float*)d_in[3];
    const float* wstr  = (const float*)d_in[4];
    const float* bstr  = (const float*)d_in[5];
    const float* wwhl  = (const float*)d_in[6];
    const float* bwhl  = (const float*)d_in[7];
    float* out = (float*)d_out;

    cudaFuncSetAttribute(k_main, cudaFuncAttributeMaxDynamicSharedMemorySize, SMEM_BYTES);

    k_transpose<<<dim3(512, 2, 8), dim3(32, 8)>>>(x);
    k_wprep<<<144, 256>>>(wmain, wrot, wstr, wwhl);
    k_coef<<<512, 256>>>(brot, bstr, bwhl);
    k_main<<<BB * HH, 128, SMEM_BYTES>>>(out);
}

// round 3
// speedup vs baseline: 1.5566x; 1.5566x over previous
#include <cuda_runtime.h>
#include <cuda_fp16.h>
#include <math.h>
#include <stdint.h>

#define BB 8
#define HH 128
#define WW 128
#define CC 64

// ---------------- scratch (allocation-free rule) ----------------
__device__ __align__(16) float g_xt[BB*HH*WW*CC];      // NHWC x
__device__ __align__(16) uint2 g_wfragB[9*8*4*32];     // mma B-fragments, fp16 [tap][j][q][lane]
__device__ __align__(16) float g_wcoef[9*CC*4];        // [tap][c][{sin,cos,str,whl}]

// ---------------- helpers ----------------
__device__ __forceinline__ uint32_t smem_u32(const void* p) {
    uint32_t a;
    asm("{ .reg .u64 t; cvta.to.shared.u64 t, %1; cvt.u32.u64 %0, t; }" : "=r"(a) : "l"(p));
    return a;
}
__device__ __forceinline__ void ldsm_x4(uint32_t* r, uint32_t addr) {
    asm volatile("ldmatrix.sync.aligned.m8n8.x4.shared.b16 {%0,%1,%2,%3}, [%4];"
                 : "=r"(r[0]), "=r"(r[1]), "=r"(r[2]), "=r"(r[3]) : "r"(addr));
}
__device__ __forceinline__ void mma16816(float* d, const uint32_t* a, uint2 b) {
    asm volatile(
        "mma.sync.aligned.m16n8k16.row.col.f32.f16.f16.f32 "
        "{%0,%1,%2,%3}, {%4,%5,%6,%7}, {%8,%9}, {%0,%1,%2,%3};"
        : "+f"(d[0]), "+f"(d[1]), "+f"(d[2]), "+f"(d[3])
        : "r"(a[0]), "r"(a[1]), "r"(a[2]), "r"(a[3]), "r"(b.x), "r"(b.y));
}

// ---------------------------------------------------------------------------
// K0: NCHW -> NHWC transpose
// ---------------------------------------------------------------------------
__global__ void k_transpose(const float* __restrict__ x) {
    __shared__ float sm[32][33];
    int b  = blockIdx.z;
    int c0 = blockIdx.y * 32;
    int s0 = blockIdx.x * 32;
    int tx = threadIdx.x, ty = threadIdx.y;   // 32 x 8
#pragma unroll
    for (int i = 0; i < 4; i++) {
        int c = c0 + ty + i * 8;
        sm[ty + i * 8][tx] = x[(b * CC + c) * (HH * WW) + s0 + tx];
    }
    __syncthreads();
#pragma unroll
    for (int i = 0; i < 4; i++) {
        int s = s0 + ty + i * 8;
        g_xt[(size_t)(b * (HH * WW) + s) * CC + c0 + tx] = sm[tx][ty + i * 8];
    }
}

// ---------------------------------------------------------------------------
// K1: weight prep — fp16 B-fragments for mma + coef weights
// B-frag (m16n8k16, .col): thread t, reg r, half s holds
//   W[k = q*16 + r*8 + (t%4)*2 + s][n = j*8 + t/4]  (k = input ch c, n = out ch o)
// ---------------------------------------------------------------------------
__global__ void k_wprep(const float* __restrict__ wmain,
                        const float* __restrict__ wrot,
                        const float* __restrict__ wstr,
                        const float* __restrict__ wwhl) {
    int idx = blockIdx.x * 256 + threadIdx.x;
    if (idx < 9 * CC * CC) {
        int o = idx % CC;
        int c = (idx / CC) % CC;
        int k = idx / (CC * CC);
        float w = wmain[(o * CC + c) * 9 + k];
        int j = o >> 3, lane_n = o & 7;
        int q = c >> 4, kk = c & 15;
        int reg = kk >> 3, r = kk & 7;
        int lane = lane_n * 4 + (r >> 1);
        int halfsel = r & 1;
        __half* dst = (__half*)g_wfragB;
        dst[(((size_t)(k * 8 + j) * 4 + q) * 32 + lane) * 4 + reg * 2 + halfsel] = __float2half(w);
    }
    if (idx < 9 * CC * 4) {
        int o   = idx & 3;
        int c   = (idx >> 2) % CC;
        int pos = idx / (CC * 4);
        float v;
        if (o == 0)      v = wrot[(0 * CC + c) * 9 + pos];
        else if (o == 1) v = wrot[(1 * CC + c) * 9 + pos];
        else if (o == 2) v = wstr[c * 9 + pos];
        else             v = wwhl[c * 9 + pos];
        g_wcoef[idx] = v;
    }
}

// ---------------------------------------------------------------------------
// K2: fused coef + deform gather + mma.sync GEMM
// CTA = one (b,h) row (128 px), 256 threads / 8 warps.
// A tile: fp16 [128 px][64 c], row stride 144 B (conflict-free ldmatrix).
// Warp w: M = px [16w, 16w+16), N = 64 o, K = 64 c per tap; 32 HMMA/tap.
// ---------------------------------------------------------------------------
#define A_STRIDE 144

__global__ void __launch_bounds__(256, 2) k_main(float* __restrict__ out,
                                                 const float* __restrict__ brot,
                                                 const float* __restrict__ bstr,
                                                 const float* __restrict__ bwhl) {
    __shared__ __align__(16) unsigned char smA[128 * A_STRIDE];
    __shared__ __align__(16) unsigned char smScratch[4096];
    int4*   ssb = (int4*)smScratch;            // [128] corner bases
    float4* ssw = (float4*)(smScratch + 2048); // [128] bilinear weights
    float4* red = (float4*)smScratch;          // [256] coef reduce (reuse)

    const int t    = threadIdx.x;
    const int wid  = t >> 5;
    const int lane = t & 31;
    const int bh   = blockIdx.x;
    const int b    = bh >> 7;
    const int h    = bh & 127;
    const float* ximg = g_xt + (size_t)b * HH * WW * CC;

    // ---- coefficient phase: 4-ch 3x3 conv over 64 c, split across 2 halves ----
    float4 cf;   // (sin, cos, wr*r, wr) — valid for t < 128
    {
        int p_ = t & 127, hf = t >> 7;
        float a0 = 0.f, a1 = 0.f, a2 = 0.f, a3 = 0.f;
#pragma unroll
        for (int tap = 0; tap < 9; tap++) {
            int y = h + tap / 3 - 1;
            int x = p_ + tap % 3 - 1;
            if ((unsigned)y < HH && (unsigned)x < WW) {
                const float4* xr  = (const float4*)(ximg + (size_t)(y * WW + x) * CC + hf * 32);
                const float4* wr4 = ((const float4*)g_wcoef) + tap * 64 + hf * 32;
#pragma unroll
                for (int c4 = 0; c4 < 8; c4++) {
                    float4 xv = xr[c4];
                    float4 w0 = wr4[c4 * 4 + 0];
                    float4 w1 = wr4[c4 * 4 + 1];
                    float4 w2 = wr4[c4 * 4 + 2];
                    float4 w3 = wr4[c4 * 4 + 3];
                    a0 += xv.x * w0.x + xv.y * w1.x + xv.z * w2.x + xv.w * w3.x;
                    a1 += xv.x * w0.y + xv.y * w1.y + xv.z * w2.y + xv.w * w3.y;
                    a2 += xv.x * w0.z + xv.y * w1.z + xv.z * w2.z + xv.w * w3.z;
                    a3 += xv.x * w0.w + xv.y * w1.w + xv.z * w2.w + xv.w * w3.w;
                }
            }
        }
        red[hf * 128 + p_] = make_float4(a0, a1, a2, a3);
        __syncthreads();
        if (t < 128) {
            float4 u = red[t], v = red[128 + t];
            float s = u.x + v.x + brot[0];
            float c = u.y + v.y + brot[1];
            float n = sqrtf(s * s + c * c + 1e-6f);
            s /= n; c /= n;
            float r  = tanhf(u.z + v.z + bstr[0]) * 1.25f + 1.75f;   // A,B
            float wl = tanhf(u.w + v.w + bwhl[0]) * 1.0f + 2.0f;     // C,D
            cf = make_float4(s, c, wl * r, wl);
        }
        __syncthreads();
    }

    const uint32_t smA_u = smem_u32(smA);
    const int m0 = wid * 16;
    // ldmatrix lane address: row = m0 + (lane&15), col-halfbyte = (lane>>4)*16
    const uint32_t ldsm_base = smA_u + (uint32_t)(m0 + (lane & 15)) * A_STRIDE + ((lane >> 4) << 4);

    float acc[8][4];
#pragma unroll
    for (int j = 0; j < 8; j++)
#pragma unroll
        for (int i = 0; i < 4; i++) acc[j][i] = 0.f;

#pragma unroll 1
    for (int k = 0; k < 9; k++) {
        // --- coords for this tap (thread t = pixel t) ---
        if (t < 128) {
            int kd3 = (k * 11) >> 5;                // k/3
            float ky = (float)(kd3 - 1);
            float kx = (float)(k - 3 * kd3 - 1);
            float o0 = ky * cf.z;                   // ky * wr * r
            float o1 = kx * cf.w;                   // kx * wr
            float py = (float)h + cf.y * o0 + cf.x * o1;
            float px = (float)t - cf.x * o0 + cf.y * o1;
            float yf = floorf(py), xf = floorf(px);
            float ly = py - yf, lx = px - xf;
            int y0 = (int)yf, x0 = (int)xf;
            int y1 = y0 + 1,  x1 = x0 + 1;
            float w00 = (1.f - ly) * (1.f - lx);
            float w01 = (1.f - ly) * lx;
            float w10 = ly * (1.f - lx);
            float w11 = ly * lx;
            float vy0 = (y0 >= 0 && y0 < HH) ? 1.f : 0.f;
            float vy1 = (y1 >= 0 && y1 < HH) ? 1.f : 0.f;
            float vx0 = (x0 >= 0 && x0 < WW) ? 1.f : 0.f;
            float vx1 = (x1 >= 0 && x1 < WW) ? 1.f : 0.f;
            w00 *= vy0 * vx0; w01 *= vy0 * vx1;
            w10 *= vy1 * vx0; w11 *= vy1 * vx1;
            int yc0 = min(max(y0, 0), HH - 1);
            int yc1 = min(max(y1, 0), HH - 1);
            int xc0 = min(max(x0, 0), WW - 1);
            int xc1 = min(max(x1, 0), WW - 1);
            int4 bs;
            bs.x = (yc0 * WW + xc0) * CC;
            bs.y = (yc0 * WW + xc1) * CC;
            bs.z = (yc1 * WW + xc0) * CC;
            bs.w = (yc1 * WW + xc1) * CC;
            ssb[t] = bs;
            ssw[t] = make_float4(w00, w01, w10, w11);
        }
        __syncthreads();   // coords ready; also all warps done reading A (prev tap)

        // --- gather + bilinear -> fp16 A tile ---
        {
            const int lc = t & 15;        // channel quad (4 ch)
            const int gg = t >> 4;        // pixel subgroup (0..15)
#pragma unroll
            for (int it = 0; it < 8; it++) {
                int p = it * 16 + gg;
                int4   bs = ssb[p];
                float4 wv = ssw[p];
                float4 v0 = *(const float4*)(ximg + bs.x + lc * 4);
                float4 v1 = *(const float4*)(ximg + bs.y + lc * 4);
                float4 v2 = *(const float4*)(ximg + bs.z + lc * 4);
                float4 v3 = *(const float4*)(ximg + bs.w + lc * 4);
                float g0 = wv.x * v0.x + wv.y * v1.x + wv.z * v2.x + wv.w * v3.x;
                float g1 = wv.x * v0.y + wv.y * v1.y + wv.z * v2.y + wv.w * v3.y;
                float g2 = wv.x * v0.z + wv.y * v1.z + wv.z * v2.z + wv.w * v3.z;
                float g3 = wv.x * v0.w + wv.y * v1.w + wv.z * v2.w + wv.w * v3.w;
                uint32_t h01, h23;   // lo = first channel
                asm("cvt.rn.f16x2.f32 %0, %1, %2;" : "=r"(h01) : "f"(g1), "f"(g0));
                asm("cvt.rn.f16x2.f32 %0, %1, %2;" : "=r"(h23) : "f"(g3), "f"(g2));
                *(uint2*)(smA + p * A_STRIDE + lc * 8) = make_uint2(h01, h23);
            }
        }
        __syncthreads();   // A tile ready

        // --- tensor phase: 4 ldmatrix.x4 (A) + 32 B-frag LDG + 32 HMMA ---
        {
            uint32_t a[4][4];
#pragma unroll
            for (int q = 0; q < 4; q++) ldsm_x4(a[q], ldsm_base + q * 32);
            const uint2* wp = g_wfragB + ((size_t)k * 8) * 4 * 32 + lane;
#pragma unroll
            for (int j = 0; j < 8; j++) {
                uint2 bfr[4];
#pragma unroll
                for (int q = 0; q < 4; q++) bfr[q] = wp[(j * 4 + q) * 32];
#pragma unroll
                for (int q = 0; q < 4; q++) mma16816(acc[j], a[q], bfr[q]);
            }
        }
    }

    // --- epilogue: scattered STG.32 to NCHW out ---
    {
        int pxa = m0 + (lane >> 2);
        float* ob = out + (((size_t)b * CC) * HH + h) * WW;
#pragma unroll
        for (int j = 0; j < 8; j++) {
            int o = j * 8 + (lane & 3) * 2;
            float* d0 = ob + (size_t)o * (HH * WW);
            float* d1 = ob + (size_t)(o + 1) * (HH * WW);
            d0[pxa]     = acc[j][0];
            d1[pxa]     = acc[j][1];
            d0[pxa + 8] = acc[j][2];
            d1[pxa + 8] = acc[j][3];
        }
    }
}

// ---------------------------------------------------------------------------
extern "C" void kernel_launch(void* const* d_in, const int* in_sizes, int n_in,
                              void* d_out, int out_size) {
    const float* x     = (const float*)d_in[0];
    const float* wmain = (const float*)d_in[1];
    const float* wrot  = (const float*)d_in[2];
    const float* brot  = (const float*)d_in[3];
    const float* wstr  = (const float*)d_in[4];
    const float* bstr  = (const float*)d_in[5];
    const float* wwhl  = (const float*)d_in[6];
    const float* bwhl  = (const float*)d_in[7];
    float* out = (float*)d_out;

    k_transpose<<<dim3(512, 2, 8), dim3(32, 8)>>>(x);
    k_wprep<<<144, 256>>>(wmain, wrot, wstr, wwhl);
    k_main<<<BB * HH, 256>>>(out, brot, bstr, bwhl);
}

// round 4
// speedup vs baseline: 2.7490x; 1.7660x over previous
#include <cuda_runtime.h>
#include <cuda_fp16.h>
#include <math.h>
#include <stdint.h>

#define BB 8
#define HH 128
#define WW 128
#define CC 64

// ---------------- scratch (allocation-free rule) ----------------
__device__ __align__(16) float  g_xt[BB*HH*WW*CC];      // NHWC x fp32 (coef conv)
__device__ __align__(16) __half g_xh[BB*HH*WW*CC];      // NHWC x fp16 (gather)
__device__ __align__(16) uint2  g_wfragB[9*8*4*32];     // mma B-fragments fp16
__device__ __align__(16) float  g_wcoef[9*CC*4];        // [tap][c][{sin,cos,str,whl}]

// ---------------- smem layout (dynamic, bytes) ----------------
#define A_STRIDE 144
#define SM_A0   0
#define SM_A1   18432
#define SM_B0   36864
#define SM_B1   45056
#define SM_SSB  53248          // int4[2][128]
#define SM_SSW  57344          // uint2[2][128]
#define SM_SCF  59392          // float4[128]
#define SMEM_REQ 61440

// ---------------- helpers ----------------
__device__ __forceinline__ uint32_t smem_u32(const void* p) {
    uint32_t a;
    asm("{ .reg .u64 t; cvta.to.shared.u64 t, %1; cvt.u32.u64 %0, t; }" : "=r"(a) : "l"(p));
    return a;
}
__device__ __forceinline__ void ldsm_x4(uint32_t* r, uint32_t addr) {
    asm volatile("ldmatrix.sync.aligned.m8n8.x4.shared.b16 {%0,%1,%2,%3}, [%4];"
                 : "=r"(r[0]), "=r"(r[1]), "=r"(r[2]), "=r"(r[3]) : "r"(addr));
}
__device__ __forceinline__ void mma16816(float* d, const uint32_t* a, uint2 b) {
    asm volatile(
        "mma.sync.aligned.m16n8k16.row.col.f32.f16.f16.f32 "
        "{%0,%1,%2,%3}, {%4,%5,%6,%7}, {%8,%9}, {%0,%1,%2,%3};"
        : "+f"(d[0]), "+f"(d[1]), "+f"(d[2]), "+f"(d[3])
        : "r"(a[0]), "r"(a[1]), "r"(a[2]), "r"(a[3]), "r"(b.x), "r"(b.y));
}

// ---------------------------------------------------------------------------
// K0: NCHW -> NHWC transpose (writes fp32 + fp16 copies)
// ---------------------------------------------------------------------------
__global__ void k_transpose(const float* __restrict__ x) {
    __shared__ float sm[32][33];
    int b  = blockIdx.z;
    int c0 = blockIdx.y * 32;
    int s0 = blockIdx.x * 32;
    int tx = threadIdx.x, ty = threadIdx.y;   // 32 x 8
#pragma unroll
    for (int i = 0; i < 4; i++) {
        int c = c0 + ty + i * 8;
        sm[ty + i * 8][tx] = x[(b * CC + c) * (HH * WW) + s0 + tx];
    }
    __syncthreads();
#pragma unroll
    for (int i = 0; i < 4; i++) {
        int s = s0 + ty + i * 8;
        float v = sm[tx][ty + i * 8];
        size_t idx = (size_t)(b * (HH * WW) + s) * CC + c0 + tx;
        g_xt[idx] = v;
        g_xh[idx] = __float2half(v);
    }
}

// ---------------------------------------------------------------------------
// K1: weight prep — fp16 B-fragments for mma + coef weights
// ---------------------------------------------------------------------------
__global__ void k_wprep(const float* __restrict__ wmain,
                        const float* __restrict__ wrot,
                        const float* __restrict__ wstr,
                        const float* __restrict__ wwhl) {
    int idx = blockIdx.x * 256 + threadIdx.x;
    if (idx < 9 * CC * CC) {
        int o = idx % CC;
        int c = (idx / CC) % CC;
        int k = idx / (CC * CC);
        float w = wmain[(o * CC + c) * 9 + k];
        int j = o >> 3, lane_n = o & 7;
        int q = c >> 4, kk = c & 15;
        int reg = kk >> 3, r = kk & 7;
        int lane = lane_n * 4 + (r >> 1);
        int halfsel = r & 1;
        __half* dst = (__half*)g_wfragB;
        dst[(((size_t)(k * 8 + j) * 4 + q) * 32 + lane) * 4 + reg * 2 + halfsel] = __float2half(w);
    }
    if (idx < 9 * CC * 4) {
        int o   = idx & 3;
        int c   = (idx >> 2) % CC;
        int pos = idx / (CC * 4);
        float v;
        if (o == 0)      v = wrot[(0 * CC + c) * 9 + pos];
        else if (o == 1) v = wrot[(1 * CC + c) * 9 + pos];
        else if (o == 2) v = wstr[c * 9 + pos];
        else             v = wwhl[c * 9 + pos];
        g_wcoef[idx] = v;
    }
}

// ---------------------------------------------------------------------------
// K2: fused coef + deform gather (fp16) + mma.sync GEMM, 1 sync/tap pipeline
// CTA = one (b,h) row (128 px), 256 threads / 8 warps.
// ---------------------------------------------------------------------------
__global__ void __launch_bounds__(256, 2) k_main(float* __restrict__ out,
                                                 const float* __restrict__ brot,
                                                 const float* __restrict__ bstr,
                                                 const float* __restrict__ bwhl) {
    extern __shared__ __align__(16) char smc[];
    int4*   ssb = (int4*)(smc + SM_SSB);    // [2][128]
    uint2*  ssw = (uint2*)(smc + SM_SSW);   // [2][128] packed fp16 weights
    float4* scf = (float4*)(smc + SM_SCF);  // [128] (sin, cos, wr*r, wr)

    const int t    = threadIdx.x;
    const int wid  = t >> 5;
    const int lane = t & 31;
    const int bh   = blockIdx.x;
    const int b    = bh >> 7;
    const int h    = bh & 127;
    const float* ximg = g_xt + (size_t)b * HH * WW * CC;
    const char*  xhimg = (const char*)(g_xh + (size_t)b * HH * WW * CC);

    // ===================== coef phase (channel-major, coalesced) =====================
    {
        const int lc = t & 15;   // channel quad
        const int gg = t >> 4;   // 0..15
        float pa[8][4];
#pragma unroll
        for (int i = 0; i < 8; i++) { pa[i][0]=0.f; pa[i][1]=0.f; pa[i][2]=0.f; pa[i][3]=0.f; }
        const float4* wcf = (const float4*)g_wcoef;
#pragma unroll
        for (int tap = 0; tap < 9; tap++) {
            int dy = tap / 3 - 1, dx = tap % 3 - 1;
            int y = h + dy;
            if ((unsigned)y >= HH) continue;
            float4 wc0 = wcf[tap * 64 + lc * 4 + 0];
            float4 wc1 = wcf[tap * 64 + lc * 4 + 1];
            float4 wc2 = wcf[tap * 64 + lc * 4 + 2];
            float4 wc3 = wcf[tap * 64 + lc * 4 + 3];
            const float* xrow = ximg + (size_t)y * WW * CC;
#pragma unroll
            for (int it = 0; it < 8; it++) {
                int px = it * 16 + gg;
                int x = px + dx;
                if ((unsigned)x >= WW) continue;
                float4 xv = *(const float4*)(xrow + x * CC + lc * 4);
                pa[it][0] += xv.x * wc0.x + xv.y * wc1.x + xv.z * wc2.x + xv.w * wc3.x;
                pa[it][1] += xv.x * wc0.y + xv.y * wc1.y + xv.z * wc2.y + xv.w * wc3.y;
                pa[it][2] += xv.x * wc0.z + xv.y * wc1.z + xv.z * wc2.z + xv.w * wc3.z;
                pa[it][3] += xv.x * wc0.w + xv.y * wc1.w + xv.z * wc2.w + xv.w * wc3.w;
            }
        }
        float b0 = brot[0], b1 = brot[1], b2 = bstr[0], b3 = bwhl[0];
#pragma unroll
        for (int it = 0; it < 8; it++) {
            float a0 = pa[it][0], a1 = pa[it][1], a2 = pa[it][2], a3 = pa[it][3];
#pragma unroll
            for (int off = 8; off >= 1; off >>= 1) {
                a0 += __shfl_xor_sync(0xffffffffu, a0, off);
                a1 += __shfl_xor_sync(0xffffffffu, a1, off);
                a2 += __shfl_xor_sync(0xffffffffu, a2, off);
                a3 += __shfl_xor_sync(0xffffffffu, a3, off);
            }
            if (lc == 0) {
                float s = a0 + b0;
                float c = a1 + b1;
                float n = sqrtf(s * s + c * c + 1e-6f);
                s /= n; c /= n;
                float r  = tanhf(a2 + b2) * 1.25f + 1.75f;
                float wl = tanhf(a3 + b3) * 1.0f + 2.0f;
                scf[it * 16 + gg] = make_float4(s, c, wl * r, wl);
            }
        }
    }

    // stage B(0) into smB0 (no hazard pre-sync)
    {
        const uint4* src = (const uint4*)g_wfragB;
        uint4* dst = (uint4*)(smc + SM_B0);
        dst[t] = src[t];
        dst[t + 256] = src[t + 256];
    }
    __syncthreads();   // scf + smB0 ready

    // coords helper (computes tap k coords into buffer bf for pixel t<128)
    // (sin, cos, wr*r, wr) = cf
    float4 cf;
    if (t < 128) cf = scf[t];

    auto coords = [&](int k, int bf) {
        if (t >= 128) return;
        int kd3 = (k * 11) >> 5;
        float ky = (float)(kd3 - 1);
        float kx = (float)(k - 3 * kd3 - 1);
        float o0 = ky * cf.z;
        float o1 = kx * cf.w;
        float py = (float)h + cf.y * o0 + cf.x * o1;
        float px = (float)t - cf.x * o0 + cf.y * o1;
        float yf = floorf(py), xf = floorf(px);
        float ly = py - yf, lx = px - xf;
        int y0 = (int)yf, x0 = (int)xf;
        int y1 = y0 + 1,  x1 = x0 + 1;
        float w00 = (1.f - ly) * (1.f - lx);
        float w01 = (1.f - ly) * lx;
        float w10 = ly * (1.f - lx);
        float w11 = ly * lx;
        float vy0 = (y0 >= 0 && y0 < HH) ? 1.f : 0.f;
        float vy1 = (y1 >= 0 && y1 < HH) ? 1.f : 0.f;
        float vx0 = (x0 >= 0 && x0 < WW) ? 1.f : 0.f;
        float vx1 = (x1 >= 0 && x1 < WW) ? 1.f : 0.f;
        w00 *= vy0 * vx0; w01 *= vy0 * vx1;
        w10 *= vy1 * vx0; w11 *= vy1 * vx1;
        int yc0 = min(max(y0, 0), HH - 1);
        int yc1 = min(max(y1, 0), HH - 1);
        int xc0 = min(max(x0, 0), WW - 1);
        int xc1 = min(max(x1, 0), WW - 1);
        int4 bs;   // BYTE offsets into fp16 image (row = 128 B)
        bs.x = (yc0 * WW + xc0) << 7;
        bs.y = (yc0 * WW + xc1) << 7;
        bs.z = (yc1 * WW + xc0) << 7;
        bs.w = (yc1 * WW + xc1) << 7;
        ssb[bf * 128 + t] = bs;
        uint32_t wlo, whi;
        asm("cvt.rn.f16x2.f32 %0, %1, %2;" : "=r"(wlo) : "f"(w01), "f"(w00));
        asm("cvt.rn.f16x2.f32 %0, %1, %2;" : "=r"(whi) : "f"(w11), "f"(w10));
        ssw[bf * 128 + t] = make_uint2(wlo, whi);
    };

    coords(0, 0);
    __syncthreads();   // ssb0/ssw0 ready

    const uint32_t smA_u = smem_u32(smc);        // A0 at offset 0
    const uint32_t smB_u = smem_u32(smc + SM_B0);
    const int m0 = wid * 16;
    const uint32_t ldsm_lane_off = (uint32_t)((lane & 15)) * A_STRIDE + ((lane >> 4) << 4);

    float acc[8][4];
#pragma unroll
    for (int j = 0; j < 8; j++)
#pragma unroll
        for (int i = 0; i < 4; i++) acc[j][i] = 0.f;

    const int lc8  = t & 7;    // channel octet (16 B fp16)
    const int gg32 = t >> 3;   // 0..31

#pragma unroll 1
    for (int k = 0; k < 9; k++) {
        const int bf = k & 1;

        // ---- gather tap k (fp16) into A[bf] ----
        {
            const int4*  sbp = ssb + bf * 128;
            const uint2* swp = ssw + bf * 128;
            char* Ab = smc + (bf ? SM_A1 : SM_A0);
#pragma unroll
            for (int it = 0; it < 4; it++) {
                int p = it * 32 + gg32;
                int4  bs = sbp[p];
                uint2 wv = swp[p];
                uint32_t u00 = __byte_perm(wv.x, 0, 0x1010);
                uint32_t u01 = __byte_perm(wv.x, 0, 0x3232);
                uint32_t u10 = __byte_perm(wv.y, 0, 0x1010);
                uint32_t u11 = __byte_perm(wv.y, 0, 0x3232);
                __half2 H00 = *(__half2*)&u00, H01 = *(__half2*)&u01;
                __half2 H10 = *(__half2*)&u10, H11 = *(__half2*)&u11;
                uint4 v0 = *(const uint4*)(xhimg + bs.x + lc8 * 16);
                uint4 v1 = *(const uint4*)(xhimg + bs.y + lc8 * 16);
                uint4 v2 = *(const uint4*)(xhimg + bs.z + lc8 * 16);
                uint4 v3 = *(const uint4*)(xhimg + bs.w + lc8 * 16);
                uint4 gv;
                {
                    __half2 a;
                    a = __hmul2(*(__half2*)&v0.x, H00);
                    a = __hfma2(*(__half2*)&v1.x, H01, a);
                    a = __hfma2(*(__half2*)&v2.x, H10, a);
                    a = __hfma2(*(__half2*)&v3.x, H11, a);
                    gv.x = *(uint32_t*)&a;
                    a = __hmul2(*(__half2*)&v0.y, H00);
                    a = __hfma2(*(__half2*)&v1.y, H01, a);
                    a = __hfma2(*(__half2*)&v2.y, H10, a);
                    a = __hfma2(*(__half2*)&v3.y, H11, a);
                    gv.y = *(uint32_t*)&a;
                    a = __hmul2(*(__half2*)&v0.z, H00);
                    a = __hfma2(*(__half2*)&v1.z, H01, a);
                    a = __hfma2(*(__half2*)&v2.z, H10, a);
                    a = __hfma2(*(__half2*)&v3.z, H11, a);
                    gv.z = *(uint32_t*)&a;
                    a = __hmul2(*(__half2*)&v0.w, H00);
                    a = __hfma2(*(__half2*)&v1.w, H01, a);
                    a = __hfma2(*(__half2*)&v2.w, H10, a);
                    a = __hfma2(*(__half2*)&v3.w, H11, a);
                    gv.w = *(uint32_t*)&a;
                }
                *(uint4*)(Ab + p * A_STRIDE + lc8 * 16) = gv;
            }
        }

        // ---- coords for tap k+1 ----
        if (k < 8) coords(k + 1, bf ^ 1);

        // ---- B prefetch (k+1) into regs ----
        uint4 bl0, bl1;
        if (k < 8) {
            const uint4* src = ((const uint4*)g_wfragB) + (size_t)(k + 1) * 512;
            bl0 = src[t];
            bl1 = src[t + 256];
        }

        __syncthreads();   // A[bf] + ssb[bf^1] ready; everyone past MMA(k-1)

        if (k < 8) {
            uint4* dst = (uint4*)(smc + SM_B0 + (bf ^ 1) * 8192);
            dst[t] = bl0;
            dst[t + 256] = bl1;
        }

        // ---- tensor phase: 4 ldmatrix.x4 (A) + B LDS + 32 HMMA ----
        {
            const uint32_t abase = smA_u + (uint32_t)(bf ? SM_A1 : SM_A0) +
                                   (uint32_t)m0 * A_STRIDE + ldsm_lane_off;
            uint32_t a[4][4];
#pragma unroll
            for (int q = 0; q < 4; q++) ldsm_x4(a[q], abase + q * 32);
            const uint2* bp = (const uint2*)(smc + SM_B0 + bf * 8192) + lane;
#pragma unroll
            for (int j = 0; j < 8; j++) {
                uint2 bfr[4];
#pragma unroll
                for (int q = 0; q < 4; q++) bfr[q] = bp[(j * 4 + q) * 32];
#pragma unroll
                for (int q = 0; q < 4; q++) mma16816(acc[j], a[q], bfr[q]);
            }
        }
    }

    // ===================== epilogue: smem-staged coalesced store =====================
    __syncthreads();
    {
        float* sout = (float*)smc;   // [64][132] floats = 33792 B
        int pxa = m0 + (lane >> 2);
#pragma unroll
        for (int j = 0; j < 8; j++) {
            int o = j * 8 + (lane & 3) * 2;
            sout[o * 132 + pxa]           = acc[j][0];
            sout[(o + 1) * 132 + pxa]     = acc[j][1];
            sout[o * 132 + pxa + 8]       = acc[j][2];
            sout[(o + 1) * 132 + pxa + 8] = acc[j][3];
        }
        __syncthreads();
#pragma unroll
        for (int it = 0; it < 8; it++) {
            int idx = it * 256 + t;
            int o = idx >> 5, pxq = idx & 31;
            float4 vv = *(const float4*)(sout + o * 132 + pxq * 4);
            *(float4*)(out + ((size_t)(b * CC + o) * HH + h) * WW + pxq * 4) = vv;
        }
    }
}

// ---------------------------------------------------------------------------
extern "C" void kernel_launch(void* const* d_in, const int* in_sizes, int n_in,
                              void* d_out, int out_size) {
    const float* x     = (const float*)d_in[0];
    const float* wmain = (const float*)d_in[1];
    const float* wrot  = (const float*)d_in[2];
    const float* brot  = (const float*)d_in[3];
    const float* wstr  = (const float*)d_in[4];
    const float* bstr  = (const float*)d_in[5];
    const float* wwhl  = (const float*)d_in[6];
    const float* bwhl  = (const float*)d_in[7];
    float* out = (float*)d_out;

    cudaFuncSetAttribute(k_main, cudaFuncAttributeMaxDynamicSharedMemorySize, SMEM_REQ);

    k_transpose<<<dim3(512, 2, 8), dim3(32, 8)>>>(x);
    k_wprep<<<144, 256>>>(wmain, wrot, wstr, wwhl);
    k_main<<<BB * HH, 256, SMEM_REQ>>>(out, brot, bstr, bwhl);
}

// round 5
// speedup vs baseline: 2.9737x; 1.0817x over previous
#include <cuda_runtime.h>
#include <cuda_fp16.h>
#include <math.h>
#include <stdint.h>

#define BB 8
#define HH 128
#define WW 128
#define CC 64

// ---------------- scratch (allocation-free rule) ----------------
__device__ __align__(16) __half g_xh[BB*HH*WW*CC];      // NHWC x fp16 (gather)
__device__ __align__(16) uint2  g_wfragB[9*8*4*32];     // mma B-fragments fp16
__device__ __align__(16) float  g_wcoef[9*CC*4];        // [tap][c][{sin,cos,str,whl}]
__device__ __align__(16) float4 g_coef[BB*HH*WW];       // (sin, cos, wr*r, wr)

// ---------------- smem layout of k_main (dynamic, bytes) ----------------
#define A_STRIDE 144
#define SM_A0   0
#define SM_A1   18432
#define SM_B0   36864          // [2][8192]
#define SM_SSB  53248          // int4[2][128]
#define SM_SSW  57344          // uint2[2][128]
#define SMEM_REQ 59392

// ---------------- helpers ----------------
__device__ __forceinline__ uint32_t smem_u32(const void* p) {
    uint32_t a;
    asm("{ .reg .u64 t; cvta.to.shared.u64 t, %1; cvt.u32.u64 %0, t; }" : "=r"(a) : "l"(p));
    return a;
}
__device__ __forceinline__ void ldsm_x4(uint32_t* r, uint32_t addr) {
    asm volatile("ldmatrix.sync.aligned.m8n8.x4.shared.b16 {%0,%1,%2,%3}, [%4];"
                 : "=r"(r[0]), "=r"(r[1]), "=r"(r[2]), "=r"(r[3]) : "r"(addr));
}
__device__ __forceinline__ void mma16816(float* d, const uint32_t* a, uint2 b) {
    asm volatile(
        "mma.sync.aligned.m16n8k16.row.col.f32.f16.f16.f32 "
        "{%0,%1,%2,%3}, {%4,%5,%6,%7}, {%8,%9}, {%0,%1,%2,%3};"
        : "+f"(d[0]), "+f"(d[1]), "+f"(d[2]), "+f"(d[3])
        : "r"(a[0]), "r"(a[1]), "r"(a[2]), "r"(a[3]), "r"(b.x), "r"(b.y));
}

// ---------------------------------------------------------------------------
// K0: weight prep — fp16 B-fragments for mma + coef weights
// ---------------------------------------------------------------------------
__global__ void k_wprep(const float* __restrict__ wmain,
                        const float* __restrict__ wrot,
                        const float* __restrict__ wstr,
                        const float* __restrict__ wwhl) {
    int idx = blockIdx.x * 256 + threadIdx.x;
    if (idx < 9 * CC * CC) {
        int o = idx % CC;
        int c = (idx / CC) % CC;
        int k = idx / (CC * CC);
        float w = wmain[(o * CC + c) * 9 + k];
        int j = o >> 3, lane_n = o & 7;
        int q = c >> 4, kk = c & 15;
        int reg = kk >> 3, r = kk & 7;
        int lane = lane_n * 4 + (r >> 1);
        int halfsel = r & 1;
        __half* dst = (__half*)g_wfragB;
        dst[(((size_t)(k * 8 + j) * 4 + q) * 32 + lane) * 4 + reg * 2 + halfsel] = __float2half(w);
    }
    if (idx < 9 * CC * 4) {
        int o   = idx & 3;
        int c   = (idx >> 2) % CC;
        int pos = idx / (CC * 4);
        float v;
        if (o == 0)      v = wrot[(0 * CC + c) * 9 + pos];
        else if (o == 1) v = wrot[(1 * CC + c) * 9 + pos];
        else if (o == 2) v = wstr[c * 9 + pos];
        else             v = wwhl[c * 9 + pos];
        g_wcoef[idx] = v;
    }
}

// ---------------------------------------------------------------------------
// K1: NCHW -> NHWC fp16 transpose
// ---------------------------------------------------------------------------
__global__ void k_transpose(const float* __restrict__ x) {
    __shared__ float sm[32][33];
    int b  = blockIdx.z;
    int c0 = blockIdx.y * 32;
    int s0 = blockIdx.x * 32;
    int tx = threadIdx.x, ty = threadIdx.y;   // 32 x 8
#pragma unroll
    for (int i = 0; i < 4; i++) {
        int c = c0 + ty + i * 8;
        sm[ty + i * 8][tx] = x[(b * CC + c) * (HH * WW) + s0 + tx];
    }
    __syncthreads();
#pragma unroll
    for (int i = 0; i < 4; i++) {
        int s = s0 + ty + i * 8;
        g_xh[(size_t)(b * (HH * WW) + s) * CC + c0 + tx] = __float2half(sm[tx][ty + i * 8]);
    }
}

// ---------------------------------------------------------------------------
// K2: coefficient convs (fp32, straight from NCHW x) -> g_coef
// CTA = one (b,h) row; 256 threads: t&127 = pixel, t>>7 = channel half.
// ---------------------------------------------------------------------------
__global__ void __launch_bounds__(256) k_coef(const float* __restrict__ x,
                                              const float* __restrict__ brot,
                                              const float* __restrict__ bstr,
                                              const float* __restrict__ bwhl) {
    __shared__ float4 swc[CC * 9];    // [c][tap] -> 4 outs
    __shared__ float4 red[256];

    const int t  = threadIdx.x;
    const int p  = t & 127;
    const int hf = t >> 7;
    const int bh = blockIdx.x;
    const int b  = bh >> 7;
    const int h  = bh & 127;

    {
        const float4* gw4 = (const float4*)g_wcoef;   // [tap*64 + c]
        for (int i = t; i < CC * 9; i += 256) {
            int c = i / 9, tap = i - c * 9;
            swc[i] = gw4[tap * 64 + c];
        }
    }
    __syncthreads();

    float a0 = 0.f, a1 = 0.f, a2 = 0.f, a3 = 0.f;
    const int c0 = hf * 32;
    const float* xb = x + ((size_t)b * CC + c0) * (HH * WW);
#pragma unroll 4
    for (int ci = 0; ci < 32; ci++) {
        const float* xc = xb + (size_t)ci * (HH * WW);
        const float4* wc = swc + (c0 + ci) * 9;
#pragma unroll
        for (int dy = 0; dy < 3; dy++) {
            int y = h + dy - 1;
            if ((unsigned)y >= HH) continue;
            const float* row = xc + y * WW;
            float xm = (p > 0)       ? row[p - 1] : 0.f;
            float x0 = row[p];
            float xp = (p < WW - 1)  ? row[p + 1] : 0.f;
            float4 wA = wc[dy * 3 + 0];
            float4 wB = wc[dy * 3 + 1];
            float4 wC = wc[dy * 3 + 2];
            a0 += xm * wA.x + x0 * wB.x + xp * wC.x;
            a1 += xm * wA.y + x0 * wB.y + xp * wC.y;
            a2 += xm * wA.z + x0 * wB.z + xp * wC.z;
            a3 += xm * wA.w + x0 * wB.w + xp * wC.w;
        }
    }
    red[t] = make_float4(a0, a1, a2, a3);
    __syncthreads();
    if (t < 128) {
        float4 u = red[t], v = red[t + 128];
        float s = u.x + v.x + brot[0];
        float c = u.y + v.y + brot[1];
        float n = sqrtf(s * s + c * c + 1e-6f);
        s /= n; c /= n;
        float r  = tanhf(u.z + v.z + bstr[0]) * 1.25f + 1.75f;
        float wl = tanhf(u.w + v.w + bwhl[0]) * 1.0f + 2.0f;
        g_coef[bh * WW + t] = make_float4(s, c, wl * r, wl);
    }
}

// ---------------------------------------------------------------------------
// K3: deform gather (fp16) + mma.sync GEMM, 1 sync/tap pipeline
// CTA = one (b,h) row (128 px), 256 threads / 8 warps.
// ---------------------------------------------------------------------------
__global__ void __launch_bounds__(256, 2) k_main(float* __restrict__ out) {
    extern __shared__ __align__(16) char smc[];
    int4*  ssb = (int4*)(smc + SM_SSB);    // [2][128]
    uint2* ssw = (uint2*)(smc + SM_SSW);   // [2][128] packed fp16 bilinear weights

    const int t    = threadIdx.x;
    const int wid  = t >> 5;
    const int lane = t & 31;
    const int bh   = blockIdx.x;
    const int b    = bh >> 7;
    const int h    = bh & 127;
    const char* xhimg = (const char*)(g_xh + (size_t)b * HH * WW * CC);

    // coefficients for this thread's pixel
    float4 cf;
    if (t < 128) cf = g_coef[bh * WW + t];

    auto coords = [&](int k, int bf) {
        if (t >= 128) return;
        int kd3 = (k * 11) >> 5;
        float ky = (float)(kd3 - 1);
        float kx = (float)(k - 3 * kd3 - 1);
        float o0 = ky * cf.z;
        float o1 = kx * cf.w;
        float py = (float)h + cf.y * o0 + cf.x * o1;
        float px = (float)t - cf.x * o0 + cf.y * o1;
        float yf = floorf(py), xf = floorf(px);
        float ly = py - yf, lx = px - xf;
        int y0 = (int)yf, x0 = (int)xf;
        int y1 = y0 + 1,  x1 = x0 + 1;
        float w00 = (1.f - ly) * (1.f - lx);
        float w01 = (1.f - ly) * lx;
        float w10 = ly * (1.f - lx);
        float w11 = ly * lx;
        float vy0 = (y0 >= 0 && y0 < HH) ? 1.f : 0.f;
        float vy1 = (y1 >= 0 && y1 < HH) ? 1.f : 0.f;
        float vx0 = (x0 >= 0 && x0 < WW) ? 1.f : 0.f;
        float vx1 = (x1 >= 0 && x1 < WW) ? 1.f : 0.f;
        w00 *= vy0 * vx0; w01 *= vy0 * vx1;
        w10 *= vy1 * vx0; w11 *= vy1 * vx1;
        int yc0 = min(max(y0, 0), HH - 1);
        int yc1 = min(max(y1, 0), HH - 1);
        int xc0 = min(max(x0, 0), WW - 1);
        int xc1 = min(max(x1, 0), WW - 1);
        int4 bs;   // BYTE offsets into fp16 image (row = 128 B)
        bs.x = (yc0 * WW + xc0) << 7;
        bs.y = (yc0 * WW + xc1) << 7;
        bs.z = (yc1 * WW + xc0) << 7;
        bs.w = (yc1 * WW + xc1) << 7;
        ssb[bf * 128 + t] = bs;
        uint32_t wlo, whi;
        asm("cvt.rn.f16x2.f32 %0, %1, %2;" : "=r"(wlo) : "f"(w01), "f"(w00));
        asm("cvt.rn.f16x2.f32 %0, %1, %2;" : "=r"(whi) : "f"(w11), "f"(w10));
        ssw[bf * 128 + t] = make_uint2(wlo, whi);
    };

    // stage B(0)
    {
        const uint4* src = (const uint4*)g_wfragB;
        uint4* dst = (uint4*)(smc + SM_B0);
        dst[t] = src[t];
        dst[t + 256] = src[t + 256];
    }
    coords(0, 0);
    __syncthreads();   // ssb0/ssw0 + smB0 ready

    const uint32_t smA_u = smem_u32(smc);
    const int m0 = wid * 16;
    const uint32_t ldsm_lane_off = (uint32_t)((lane & 15)) * A_STRIDE + ((lane >> 4) << 4);

    float acc[8][4];
#pragma unroll
    for (int j = 0; j < 8; j++)
#pragma unroll
        for (int i = 0; i < 4; i++) acc[j][i] = 0.f;

    const int lc8  = t & 7;    // channel octet (16 B fp16)
    const int gg32 = t >> 3;   // 0..31

#pragma unroll 1
    for (int k = 0; k < 9; k++) {
        const int bf = k & 1;

        // ---- gather tap k (fp16) into A[bf] ----
        {
            const int4*  sbp = ssb + bf * 128;
            const uint2* swp = ssw + bf * 128;
            char* Ab = smc + (bf ? SM_A1 : SM_A0);
#pragma unroll
            for (int it = 0; it < 4; it++) {
                int p = it * 32 + gg32;
                int4  bs = sbp[p];
                uint2 wv = swp[p];
                uint32_t u00 = __byte_perm(wv.x, 0, 0x1010);
                uint32_t u01 = __byte_perm(wv.x, 0, 0x3232);
                uint32_t u10 = __byte_perm(wv.y, 0, 0x1010);
                uint32_t u11 = __byte_perm(wv.y, 0, 0x3232);
                __half2 H00 = *(__half2*)&u00, H01 = *(__half2*)&u01;
                __half2 H10 = *(__half2*)&u10, H11 = *(__half2*)&u11;
                uint4 v0 = *(const uint4*)(xhimg + bs.x + lc8 * 16);
                uint4 v1 = *(const uint4*)(xhimg + bs.y + lc8 * 16);
                uint4 v2 = *(const uint4*)(xhimg + bs.z + lc8 * 16);
                uint4 v3 = *(const uint4*)(xhimg + bs.w + lc8 * 16);
                uint4 gv;
                {
                    __half2 a;
                    a = __hmul2(*(__half2*)&v0.x, H00);
                    a = __hfma2(*(__half2*)&v1.x, H01, a);
                    a = __hfma2(*(__half2*)&v2.x, H10, a);
                    a = __hfma2(*(__half2*)&v3.x, H11, a);
                    gv.x = *(uint32_t*)&a;
                    a = __hmul2(*(__half2*)&v0.y, H00);
                    a = __hfma2(*(__half2*)&v1.y, H01, a);
                    a = __hfma2(*(__half2*)&v2.y, H10, a);
                    a = __hfma2(*(__half2*)&v3.y, H11, a);
                    gv.y = *(uint32_t*)&a;
                    a = __hmul2(*(__half2*)&v0.z, H00);
                    a = __hfma2(*(__half2*)&v1.z, H01, a);
                    a = __hfma2(*(__half2*)&v2.z, H10, a);
                    a = __hfma2(*(__half2*)&v3.z, H11, a);
                    gv.z = *(uint32_t*)&a;
                    a = __hmul2(*(__half2*)&v0.w, H00);
                    a = __hfma2(*(__half2*)&v1.w, H01, a);
                    a = __hfma2(*(__half2*)&v2.w, H10, a);
                    a = __hfma2(*(__half2*)&v3.w, H11, a);
                    gv.w = *(uint32_t*)&a;
                }
                *(uint4*)(Ab + p * A_STRIDE + lc8 * 16) = gv;
            }
        }

        // ---- coords for tap k+1 ----
        if (k < 8) coords(k + 1, bf ^ 1);

        // ---- B prefetch (k+1) into regs ----
        uint4 bl0, bl1;
        if (k < 8) {
            const uint4* src = ((const uint4*)g_wfragB) + (size_t)(k + 1) * 512;
            bl0 = src[t];
            bl1 = src[t + 256];
        }

        __syncthreads();   // A[bf] + ssb[bf^1] ready; everyone past MMA(k-1)

        if (k < 8) {
            uint4* dst = (uint4*)(smc + SM_B0 + (bf ^ 1) * 8192);
            dst[t] = bl0;
            dst[t + 256] = bl1;
        }

        // ---- tensor phase: 4 ldmatrix.x4 (A) + B LDS + 32 HMMA ----
        {
            const uint32_t abase = smA_u + (uint32_t)(bf ? SM_A1 : SM_A0) +
                                   (uint32_t)m0 * A_STRIDE + ldsm_lane_off;
            uint32_t a[4][4];
#pragma unroll
            for (int q = 0; q < 4; q++) ldsm_x4(a[q], abase + q * 32);
            const uint2* bp = (const uint2*)(smc + SM_B0 + bf * 8192) + lane;
#pragma unroll
            for (int j = 0; j < 8; j++) {
                uint2 bfr[4];
#pragma unroll
                for (int q = 0; q < 4; q++) bfr[q] = bp[(j * 4 + q) * 32];
#pragma unroll
                for (int q = 0; q < 4; q++) mma16816(acc[j], a[q], bfr[q]);
            }
        }
    }

    // ===================== epilogue: smem-staged coalesced store =====================
    __syncthreads();
    {
        float* sout = (float*)smc;   // [64][132] floats = 33792 B
        int pxa = m0 + (lane >> 2);
#pragma unroll
        for (int j = 0; j < 8; j++) {
            int o = j * 8 + (lane & 3) * 2;
            sout[o * 132 + pxa]           = acc[j][0];
            sout[(o + 1) * 132 + pxa]     = acc[j][1];
            sout[o * 132 + pxa + 8]       = acc[j][2];
            sout[(o + 1) * 132 + pxa + 8] = acc[j][3];
        }
        __syncthreads();
#pragma unroll
        for (int it = 0; it < 8; it++) {
            int idx = it * 256 + t;
            int o = idx >> 5, pxq = idx & 31;
            float4 vv = *(const float4*)(sout + o * 132 + pxq * 4);
            *(float4*)(out + ((size_t)(b * CC + o) * HH + h) * WW + pxq * 4) = vv;
        }
    }
}

// ---------------------------------------------------------------------------
extern "C" void kernel_launch(void* const* d_in, const int* in_sizes, int n_in,
                              void* d_out, int out_size) {
    const float* x     = (const float*)d_in[0];
    const float* wmain = (const float*)d_in[1];
    const float* wrot  = (const float*)d_in[2];
    const float* brot  = (const float*)d_in[3];
    const float* wstr  = (const float*)d_in[4];
    const float* bstr  = (const float*)d_in[5];
    const float* wwhl  = (const float*)d_in[6];
    const float* bwhl  = (const float*)d_in[7];
    float* out = (float*)d_out;

    cudaFuncSetAttribute(k_main, cudaFuncAttributeMaxDynamicSharedMemorySize, SMEM_REQ);

    k_wprep<<<144, 256>>>(wmain, wrot, wstr, wwhl);
    k_transpose<<<dim3(512, 2, 8), dim3(32, 8)>>>(x);
    k_coef<<<BB * HH, 256>>>(x, brot, bstr, bwhl);
    k_main<<<BB * HH, 256, SMEM_REQ>>>(out);
}